// round 14
// baseline (speedup 1.0000x reference)
#include <cuda_runtime.h>
#include <cuda_fp16.h>

#define NN 100000
#define EE 3200000
#define NPW 4                     // nodes per warp in k_prop64

// ------------------------- scratch (static device memory) -------------------
// g_deg / g_cnt rely on static zero-init for the FIRST run; k_final re-zeroes
// them at the end of every run so each graph replay sees zeros again.
__device__ float  g_deg[NN];
__device__ float  g_dinv[NN];
__device__ int    g_cnt[NN];
__device__ int    g_rowptr[NN + 1];
__device__ int    g_cursor[NN];
__device__ int2   g_csr[EE];             // (src, norm bits), grouped by dst
__device__ float  g_x16[4][NN * 16];     // layer-1 hops h1..h4 (F=16, fp32)
__device__ float  g_h[4][NN * 64];       // hidden hops h1..h4 (fp32, mm input)
__device__ __half g_h16[4][NN * 64];     // fp16 shadows of g_h (gather input)
__device__ float  g_outA[NN * 64];       // layer outputs ping (fp32)
__device__ float  g_outB[NN * 64];       // layer outputs pong (fp32)
__device__ __half g_outAh[NN * 64];      // fp16 shadow of outA
__device__ __half g_outBh[NN * 64];      // fp16 shadow of outB

__device__ __forceinline__ const __half* hbuf16(int s) {
    switch (s) {
        case 0: return g_h16[0];
        case 1: return g_h16[1];
        case 2: return g_h16[2];
        case 3: return g_h16[3];
        case 4: return g_outAh;
        default: return g_outBh;
    }
}

// warp-local edge_index dtype detect: int64 ids < 2^17 have all-odd-words zero
__device__ __forceinline__ int detect64(const int* ei, int lane) {
    unsigned odd = __ballot_sync(0xffffffffu,
                                 (lane < 16) ? (ei[2 * lane + 1] != 0) : false);
    return odd == 0u;
}

__device__ __forceinline__ int edge_at(const int* ei, int is64, long long pos) {
    if (is64) return (int)((const long long*)ei)[pos];
    return ei[pos];
}

// packed fp32x2 helpers (sm_103a dual-FMA pipe, full fp32 precision)
__device__ __forceinline__ void fma2(unsigned long long& d,
                                     unsigned long long a,
                                     unsigned long long b) {
    asm("fma.rn.f32x2 %0, %1, %2, %0;" : "+l"(d) : "l"(a), "l"(b));
}
__device__ __forceinline__ unsigned long long add2(unsigned long long a,
                                                   unsigned long long b) {
    unsigned long long r;
    asm("add.rn.f32x2 %0, %1, %2;" : "=l"(r) : "l"(a), "l"(b));
    return r;
}
__device__ __forceinline__ unsigned long long pack2(float x, float y) {
    unsigned long long r;
    asm("mov.b64 %0, {%1, %2};" : "=l"(r) : "f"(x), "f"(y));
    return r;
}
__device__ __forceinline__ float2 unpack2(unsigned long long v) {
    float lo, hi;
    asm("mov.b64 {%0, %1}, %2;" : "=f"(lo), "=f"(hi) : "l"(v));
    return make_float2(lo, hi);
}

// ------------------------- 0: deg + cnt histogram ----------------------------
__global__ void k_cntdeg(const int* __restrict__ ei,
                         const float* __restrict__ ew) {
    int e = blockIdx.x * 256 + threadIdx.x;
    int lane = threadIdx.x & 31;
    int is64 = detect64(ei, lane);
    if (e < EE) {
        int d = edge_at(ei, is64, (long long)EE + e);
        if ((unsigned)d < (unsigned)NN) {
            atomicAdd(&g_deg[d], ew[e]);
            atomicAdd(&g_cnt[d], 1);
        }
    }
}

// ------------------------- 1: single-launch scan + rsqrt ---------------------
__global__ void k_scan() {
    __shared__ int ws[32];
    __shared__ int stot;
    int t = threadIdx.x, lane = t & 31, wid = t >> 5;
    int running = 0;
    for (int tile = 0; tile < 98; tile++) {       // 98*1024 >= NN
        int i = tile * 1024 + t;
        int v = 0;
        if (i < NN) {
            v = g_cnt[i];
            float d = g_deg[i];
            g_dinv[i] = (d > 0.f) ? rsqrtf(d) : 0.f;
        }
        int inc = v;
        #pragma unroll
        for (int off = 1; off < 32; off <<= 1) {
            int o = __shfl_up_sync(0xffffffffu, inc, off);
            if (lane >= off) inc += o;
        }
        if (lane == 31) ws[wid] = inc;
        __syncthreads();
        if (wid == 0) {
            int wv = ws[lane];
            int winc = wv;
            #pragma unroll
            for (int off = 1; off < 32; off <<= 1) {
                int o = __shfl_up_sync(0xffffffffu, winc, off);
                if (lane >= off) winc += o;
            }
            ws[lane] = winc - wv;
            if (lane == 31) stot = winc;
        }
        __syncthreads();
        int excl = running + ws[wid] + inc - v;
        if (i < NN) { g_rowptr[i] = excl; g_cursor[i] = excl; }
        running += stot;
        __syncthreads();
    }
    if (t == 0) g_rowptr[NN] = running;
}

// ------------------------- 2: scatter with norm ------------------------------
__global__ void k_scatter(const int* __restrict__ ei,
                          const float* __restrict__ ew) {
    int e = blockIdx.x * 256 + threadIdx.x;
    int lane = threadIdx.x & 31;
    int is64 = detect64(ei, lane);
    if (e < EE) {
        int s = edge_at(ei, is64, e);
        int d = edge_at(ei, is64, (long long)EE + e);
        if ((unsigned)s < (unsigned)NN && (unsigned)d < (unsigned)NN) {
            float nm = g_dinv[s] * ew[e] * g_dinv[d];
            int pos = atomicAdd(&g_cursor[d], 1);
            g_csr[pos] = make_int2(s, __float_as_int(nm));
        }
    }
}

// ------------------------- propagation ---------------------------------------
// F=16 (fp32): 4 lanes per edge (float4 row = 64B), 8 edges per warp-step.
__global__ void k_prop16(const float* __restrict__ xext, int in_sel, int out_sel) {
    int gid = blockIdx.x * blockDim.x + threadIdx.x;
    int n = gid >> 5, lane = gid & 31;
    int f4 = lane & 3, slot = lane >> 2;
    const float4* hin = (in_sel < 0) ? (const float4*)xext
                                     : (const float4*)g_x16[in_sel];
    float4* hout = (float4*)g_x16[out_sel];
    int s0 = g_rowptr[n], s1 = g_rowptr[n + 1];
    unsigned long long acc[2] = {0ULL, 0ULL};
    for (int base = s0; base < s1; base += 8) {
        int idx = base + slot;                       // 8 slots = 8 edges
        int2 e = (idx < s1) ? __ldg(&g_csr[idx]) : make_int2(0, 0);
        float ww = __int_as_float(e.y);
        float4 r = hin[e.x * 4 + f4];
        unsigned long long w2 = pack2(ww, ww);
        fma2(acc[0], pack2(r.x, r.y), w2);
        fma2(acc[1], pack2(r.z, r.w), w2);
    }
    float2 v0 = unpack2(acc[0]), v1 = unpack2(acc[1]);
    float a0 = v0.x, a1 = v0.y, a2 = v1.x, a3 = v1.y;
    #pragma unroll
    for (int off = 4; off <= 16; off <<= 1) {        // reduce 8 slots
        a0 += __shfl_xor_sync(0xffffffffu, a0, off);
        a1 += __shfl_xor_sync(0xffffffffu, a1, off);
        a2 += __shfl_xor_sync(0xffffffffu, a2, off);
        a3 += __shfl_xor_sync(0xffffffffu, a3, off);
    }
    if (lane < 4) hout[n * 4 + f4] = make_float4(a0, a1, a2, a3);
}

// F=64, fp16 gathers, NPW nodes per warp interleaved.
// Row = 64 half = 128B = 8 uint4. 8 lanes/edge, 4 edge-slots, 32-edge chunks.
// 4 independent accumulator sets per warp -> 4x memory-level parallelism.
__global__ void k_prop64(int in_sel, int out_sel) {
    int gid = blockIdx.x * blockDim.x + threadIdx.x;
    int w = gid >> 5, lane = gid & 31;
    int n0 = w * NPW;
    int f8 = lane & 7, slot = lane >> 3;
    const uint4* hin = (const uint4*)hbuf16(in_sel);   // row = 8 uint4
    int s0[NPW], s1[NPW];
    int maxd = 0;
    #pragma unroll
    for (int m = 0; m < NPW; m++) {
        s0[m] = __ldg(&g_rowptr[n0 + m]);
        s1[m] = __ldg(&g_rowptr[n0 + m + 1]);
        maxd = max(maxd, s1[m] - s0[m]);
    }
    unsigned long long acc[NPW][4];
    #pragma unroll
    for (int m = 0; m < NPW; m++)
        #pragma unroll
        for (int i = 0; i < 4; i++) acc[m][i] = 0ULL;

    for (int c = 0; c < maxd; c += 32) {
        #pragma unroll
        for (int jj = 0; jj < 8; jj++) {
            int2 e[NPW];
            #pragma unroll
            for (int m = 0; m < NPW; m++) {
                int idx = s0[m] + c + jj * 4 + slot;   // 4 edges per sub-step
                e[m] = (idx < s1[m]) ? __ldg(&g_csr[idx]) : make_int2(0, 0);
            }
            #pragma unroll
            for (int m = 0; m < NPW; m++) {
                float ww = __int_as_float(e[m].y);
                uint4 r = hin[e[m].x * 8 + f8];        // 8 halves = 16B
                unsigned long long w2 = pack2(ww, ww);
                float2 f0 = __half22float2(*(const __half2*)&r.x);
                float2 f1 = __half22float2(*(const __half2*)&r.y);
                float2 f2 = __half22float2(*(const __half2*)&r.z);
                float2 f3 = __half22float2(*(const __half2*)&r.w);
                fma2(acc[m][0], pack2(f0.x, f0.y), w2);
                fma2(acc[m][1], pack2(f1.x, f1.y), w2);
                fma2(acc[m][2], pack2(f2.x, f2.y), w2);
                fma2(acc[m][3], pack2(f3.x, f3.y), w2);
            }
        }
    }
    // reduce the 4 edge-slots per node (packed adds), then store
    #pragma unroll
    for (int m = 0; m < NPW; m++) {
        #pragma unroll
        for (int off = 8; off <= 16; off <<= 1)
            #pragma unroll
            for (int i = 0; i < 4; i++) {
                unsigned long long o = __shfl_xor_sync(0xffffffffu, acc[m][i], off);
                acc[m][i] = add2(acc[m][i], o);
            }
        if (lane < 8) {
            int n = n0 + m;
            float2 v0 = unpack2(acc[m][0]), v1 = unpack2(acc[m][1]);
            float2 v2 = unpack2(acc[m][2]), v3 = unpack2(acc[m][3]);
            float4* o4 = (float4*)(g_h[out_sel] + (size_t)n * 64 + f8 * 8);
            o4[0] = make_float4(v0.x, v0.y, v1.x, v1.y);
            o4[1] = make_float4(v2.x, v2.y, v3.x, v3.y);
            __half2 p0 = __floats2half2_rn(v0.x, v0.y);
            __half2 p1 = __floats2half2_rn(v1.x, v1.y);
            __half2 p2 = __floats2half2_rn(v2.x, v2.y);
            __half2 p3 = __floats2half2_rn(v3.x, v3.y);
            uint4 hv;
            hv.x = *(const unsigned*)&p0;
            hv.y = *(const unsigned*)&p1;
            hv.z = *(const unsigned*)&p2;
            hv.w = *(const unsigned*)&p3;
            *(uint4*)(g_h16[out_sel] + (size_t)n * 64 + f8 * 8) = hv;
        }
    }
}

// ------------------------- fused hop-GEMM (f32x2 pipe, R7 tile) --------------
// block: 256 threads = 256 nodes x 64 j; thread: 8 nodes x 8 j (4 j-pairs).
// Reads fp32 hops; writes fp32 output + fp16 shadow (next layer's gathers).
template <int F>
__device__ __forceinline__ void mm_body(const float* __restrict__ h0,
                                        const float* __restrict__ h1,
                                        const float* __restrict__ h2,
                                        const float* __restrict__ h3,
                                        const float* __restrict__ h4,
                                        const float* __restrict__ W,
                                        const float* __restrict__ b,
                                        float* __restrict__ out,
                                        __half* __restrict__ outh,
                                        float* shW) {
    const float* hs[5] = {h0, h1, h2, h3, h4};
    int t  = threadIdx.x;
    int n0 = blockIdx.x * 256;
    int tn = (t & 31) * 8;          // 32 node-groups
    int tj = (t >> 5) * 8;          // 8 j-groups

    unsigned long long acc2[8][4];
    #pragma unroll
    for (int p = 0; p < 8; p++)
        #pragma unroll
        for (int jp = 0; jp < 4; jp++) acc2[p][jp] = 0ULL;

    for (int k = 0; k < 5; k++) {
        __syncthreads();
        {
            const float4* Wk  = (const float4*)(W + k * F * 64);
            float4*       sh4 = (float4*)shW;
            for (int idx = t; idx < F * 16; idx += 256) sh4[idx] = Wk[idx];
        }
        __syncthreads();
        const unsigned long long* shW2 = (const unsigned long long*)shW;
        const float* hk = hs[k];
        for (int ic = 0; ic < F / 4; ic++) {
            float4 a[8];
            #pragma unroll
            for (int p = 0; p < 8; p++) {
                int n = n0 + tn + p;
                a[p] = (n < NN) ? *(const float4*)(hk + (size_t)n * F + ic * 4)
                                : make_float4(0.f, 0.f, 0.f, 0.f);
            }
            #pragma unroll
            for (int q = 0; q < 4; q++) {
                int i = ic * 4 + q;
                unsigned long long w2[4];
                #pragma unroll
                for (int jp = 0; jp < 4; jp++)
                    w2[jp] = shW2[(i * 64 + tj) / 2 + jp];
                #pragma unroll
                for (int p = 0; p < 8; p++) {
                    float av = (q == 0) ? a[p].x : (q == 1) ? a[p].y
                             : (q == 2) ? a[p].z : a[p].w;
                    unsigned long long av2 = pack2(av, av);
                    #pragma unroll
                    for (int jp = 0; jp < 4; jp++)
                        fma2(acc2[p][jp], av2, w2[jp]);
                }
            }
        }
    }
    float bb[8];
    #pragma unroll
    for (int jj = 0; jj < 8; jj++) bb[jj] = b[tj + jj];
    #pragma unroll
    for (int p = 0; p < 8; p++) {
        int n = n0 + tn + p;
        if (n < NN) {
            float y[8];
            #pragma unroll
            for (int jp = 0; jp < 4; jp++) {
                float2 v = unpack2(acc2[p][jp]);
                y[jp * 2]     = v.x + bb[jp * 2];
                y[jp * 2 + 1] = v.y + bb[jp * 2 + 1];
            }
            #pragma unroll
            for (int jj = 0; jj < 8; jj++)
                y[jj] = (y[jj] >= 0.f) ? y[jj] : 0.01f * y[jj];
            float4* o4 = (float4*)(out + (size_t)n * 64 + tj);
            o4[0] = make_float4(y[0], y[1], y[2], y[3]);
            o4[1] = make_float4(y[4], y[5], y[6], y[7]);
            __half2 p0 = __floats2half2_rn(y[0], y[1]);
            __half2 p1 = __floats2half2_rn(y[2], y[3]);
            __half2 p2 = __floats2half2_rn(y[4], y[5]);
            __half2 p3 = __floats2half2_rn(y[6], y[7]);
            uint4 hv;
            hv.x = *(const unsigned*)&p0;
            hv.y = *(const unsigned*)&p1;
            hv.z = *(const unsigned*)&p2;
            hv.w = *(const unsigned*)&p3;
            *(uint4*)(outh + (size_t)n * 64 + tj) = hv;
        }
    }
}

__global__ void k_mm16(const float* __restrict__ x,
                       const float* __restrict__ W,
                       const float* __restrict__ b) {
    __shared__ __align__(16) float shW[16 * 64];
    mm_body<16>(x, g_x16[0], g_x16[1], g_x16[2], g_x16[3],
                W, b, g_outA, g_outAh, shW);
}

__global__ void k_mm64(int in_sel, const float* __restrict__ W,
                       const float* __restrict__ b, int out_sel) {
    __shared__ __align__(16) float shW[64 * 64];
    const float* h0   = (in_sel == 4) ? g_outA : g_outB;
    float*       out  = (out_sel == 4) ? g_outA : g_outB;
    __half*      outh = (out_sel == 4) ? g_outAh : g_outBh;
    mm_body<64>(h0, g_h[0], g_h[1], g_h[2], g_h[3], W, b, out, outh, shW);
}

// ------------------------- final head + state restore ------------------------
__global__ void k_final(const float* __restrict__ Wout,
                        const float* __restrict__ bout,
                        float* __restrict__ out) {
    int gid = blockIdx.x * blockDim.x + threadIdx.x;
    int n = gid >> 5, lane = gid & 31;
    float2 v = ((const float2*)g_outA)[n * 32 + lane];
    float2 w = ((const float2*)Wout)[lane];
    float a = v.x * w.x + v.y * w.y;
    #pragma unroll
    for (int off = 16; off > 0; off >>= 1)
        a += __shfl_xor_sync(0xffffffffu, a, off);
    if (lane == 0) {
        out[n] = a + bout[0];
        g_cnt[n] = 0;            // restore zeros for next graph replay
        g_deg[n] = 0.f;
    }
}

// ------------------------- launch -------------------------------------------
extern "C" void kernel_launch(void* const* d_in, const int* in_sizes, int n_in,
                              void* d_out, int out_size) {
    const float* x    = (const float*)d_in[0];
    const int*   ei   = (const int*)d_in[1];     // dtype auto-detected per warp
    const float* ew   = (const float*)d_in[2];
    const float* W1   = (const float*)d_in[4];
    const float* b1   = (const float*)d_in[5];
    const float* W2   = (const float*)d_in[6];
    const float* b2   = (const float*)d_in[7];
    const float* Wout = (const float*)d_in[8];
    const float* bout = (const float*)d_in[9];
    float*       out  = (float*)d_out;

    const int NB_E  = (EE + 255) / 256;
    const int NB_W  = (NN * 32) / 256;        // warp-per-node: 12500 blocks
    const int NB_P  = (NN / NPW + 7) / 8;     // prop64: 4 nodes/warp, 3125 blocks
    const int NB_M  = (NN + 255) / 256;       // mm kernels: 391 blocks

    // CSR build: 3 launches (deg/cnt zeros restored by k_final each run)
    k_cntdeg <<<NB_E, 256>>>(ei, ew);       // 0
    k_scan   <<<1, 1024>>>();               // 1
    k_scatter<<<NB_E, 256>>>(ei, ew);       // 2

    // Layer 1 (F_IN=16 -> 64), all fp32
    k_prop16<<<NB_W, 256>>>(x, -1, 0);      // 3 <- ncu capture slot
    k_prop16<<<NB_W, 256>>>(x,  0, 1);
    k_prop16<<<NB_W, 256>>>(x,  1, 2);
    k_prop16<<<NB_W, 256>>>(x,  2, 3);
    k_mm16  <<<NB_M, 256>>>(x, W1, b1);

    // Layer 2 (64 -> 64): in A(4) -> out B(5), fp16 gathers, 4 nodes/warp
    k_prop64<<<NB_P, 256>>>(4, 0);
    k_prop64<<<NB_P, 256>>>(0, 1);
    k_prop64<<<NB_P, 256>>>(1, 2);
    k_prop64<<<NB_P, 256>>>(2, 3);
    k_mm64  <<<NB_M, 256>>>(4, W2, b2, 5);

    // Layer 3 (64 -> 64): in B(5) -> out A(4), fp16 gathers, 4 nodes/warp
    k_prop64<<<NB_P, 256>>>(5, 0);
    k_prop64<<<NB_P, 256>>>(0, 1);
    k_prop64<<<NB_P, 256>>>(1, 2);
    k_prop64<<<NB_P, 256>>>(2, 3);
    k_mm64  <<<NB_M, 256>>>(5, W2 + 5 * 64 * 64, b2 + 64, 4);

    // Regression head + scratch restore
    k_final<<<NB_W, 256>>>(Wout, bout, out);
}

// round 15
// speedup vs baseline: 1.6812x; 1.6812x over previous
#include <cuda_runtime.h>
#include <cuda_fp16.h>

#define NN 100000
#define EE 3200000

// ------------------------- scratch (static device memory) -------------------
// g_deg / g_cnt rely on static zero-init for the FIRST run; k_final re-zeroes
// them at the end of every run so each graph replay sees zeros again.
__device__ float  g_deg[NN];
__device__ float  g_dinv[NN];
__device__ int    g_cnt[NN];
__device__ int    g_rowptr[NN + 1];
__device__ int    g_cursor[NN];
__device__ int2   g_csr[EE];             // (src, norm bits), grouped by dst
__device__ float  g_x16[4][NN * 16];     // layer-1 hops h1..h4 (F=16, fp32)
__device__ float  g_h[4][NN * 64];       // hidden hops h1..h4 (fp32, mm input)
__device__ __half g_h16[4][NN * 64];     // fp16 shadows of g_h (gather input)
__device__ float  g_outA[NN * 64];       // layer outputs ping (fp32)
__device__ float  g_outB[NN * 64];       // layer outputs pong (fp32)
__device__ __half g_outAh[NN * 64];      // fp16 shadow of outA
__device__ __half g_outBh[NN * 64];      // fp16 shadow of outB

__device__ __forceinline__ const __half* hbuf16(int s) {
    switch (s) {
        case 0: return g_h16[0];
        case 1: return g_h16[1];
        case 2: return g_h16[2];
        case 3: return g_h16[3];
        case 4: return g_outAh;
        default: return g_outBh;
    }
}

// warp-local edge_index dtype detect: int64 ids < 2^17 have all-odd-words zero
__device__ __forceinline__ int detect64(const int* ei, int lane) {
    unsigned odd = __ballot_sync(0xffffffffu,
                                 (lane < 16) ? (ei[2 * lane + 1] != 0) : false);
    return odd == 0u;
}

__device__ __forceinline__ int edge_at(const int* ei, int is64, long long pos) {
    if (is64) return (int)((const long long*)ei)[pos];
    return ei[pos];
}

// packed fp32x2 helpers (sm_103a dual-FMA pipe, full fp32 precision)
__device__ __forceinline__ void fma2(unsigned long long& d,
                                     unsigned long long a,
                                     unsigned long long b) {
    asm("fma.rn.f32x2 %0, %1, %2, %0;" : "+l"(d) : "l"(a), "l"(b));
}
__device__ __forceinline__ unsigned long long add2(unsigned long long a,
                                                   unsigned long long b) {
    unsigned long long r;
    asm("add.rn.f32x2 %0, %1, %2;" : "=l"(r) : "l"(a), "l"(b));
    return r;
}
__device__ __forceinline__ unsigned long long pack2(float x, float y) {
    unsigned long long r;
    asm("mov.b64 %0, {%1, %2};" : "=l"(r) : "f"(x), "f"(y));
    return r;
}
__device__ __forceinline__ float2 unpack2(unsigned long long v) {
    float lo, hi;
    asm("mov.b64 {%0, %1}, %2;" : "=f"(lo), "=f"(hi) : "l"(v));
    return make_float2(lo, hi);
}

// ------------------------- 0: deg + cnt histogram ----------------------------
__global__ void k_cntdeg(const int* __restrict__ ei,
                         const float* __restrict__ ew) {
    int e = blockIdx.x * 256 + threadIdx.x;
    int lane = threadIdx.x & 31;
    int is64 = detect64(ei, lane);
    if (e < EE) {
        int d = edge_at(ei, is64, (long long)EE + e);
        if ((unsigned)d < (unsigned)NN) {
            atomicAdd(&g_deg[d], ew[e]);
            atomicAdd(&g_cnt[d], 1);
        }
    }
}

// ------------------------- 1: single-launch scan + rsqrt ---------------------
__global__ void k_scan() {
    __shared__ int ws[32];
    __shared__ int stot;
    int t = threadIdx.x, lane = t & 31, wid = t >> 5;
    int running = 0;
    for (int tile = 0; tile < 98; tile++) {       // 98*1024 >= NN
        int i = tile * 1024 + t;
        int v = 0;
        if (i < NN) {
            v = g_cnt[i];
            float d = g_deg[i];
            g_dinv[i] = (d > 0.f) ? rsqrtf(d) : 0.f;
        }
        int inc = v;
        #pragma unroll
        for (int off = 1; off < 32; off <<= 1) {
            int o = __shfl_up_sync(0xffffffffu, inc, off);
            if (lane >= off) inc += o;
        }
        if (lane == 31) ws[wid] = inc;
        __syncthreads();
        if (wid == 0) {
            int wv = ws[lane];
            int winc = wv;
            #pragma unroll
            for (int off = 1; off < 32; off <<= 1) {
                int o = __shfl_up_sync(0xffffffffu, winc, off);
                if (lane >= off) winc += o;
            }
            ws[lane] = winc - wv;
            if (lane == 31) stot = winc;
        }
        __syncthreads();
        int excl = running + ws[wid] + inc - v;
        if (i < NN) { g_rowptr[i] = excl; g_cursor[i] = excl; }
        running += stot;
        __syncthreads();
    }
    if (t == 0) g_rowptr[NN] = running;
}

// ------------------------- 2: scatter with norm ------------------------------
__global__ void k_scatter(const int* __restrict__ ei,
                          const float* __restrict__ ew) {
    int e = blockIdx.x * 256 + threadIdx.x;
    int lane = threadIdx.x & 31;
    int is64 = detect64(ei, lane);
    if (e < EE) {
        int s = edge_at(ei, is64, e);
        int d = edge_at(ei, is64, (long long)EE + e);
        if ((unsigned)s < (unsigned)NN && (unsigned)d < (unsigned)NN) {
            float nm = g_dinv[s] * ew[e] * g_dinv[d];
            int pos = atomicAdd(&g_cursor[d], 1);
            g_csr[pos] = make_int2(s, __float_as_int(nm));
        }
    }
}

// ------------------------- propagation (batched loads) -----------------------
// F=16 (fp32): 4 lanes/edge (float4 row = 64B), 8 edge-slots, 32-edge chunks.
// Phase A: 4 csr loads batched; phase B: 4 row gathers batched; phase C: FMA.
__global__ void k_prop16(const float* __restrict__ xext, int in_sel, int out_sel) {
    int gid = blockIdx.x * blockDim.x + threadIdx.x;
    int n = gid >> 5, lane = gid & 31;
    int f4 = lane & 3, slot = lane >> 2;
    const float4* hin = (in_sel < 0) ? (const float4*)xext
                                     : (const float4*)g_x16[in_sel];
    float4* hout = (float4*)g_x16[out_sel];
    int s0 = g_rowptr[n], s1 = g_rowptr[n + 1];
    unsigned long long acc[2] = {0ULL, 0ULL};
    for (int base = s0; base < s1; base += 32) {
        int2 e[4];
        #pragma unroll
        for (int jj = 0; jj < 4; jj++) {
            int idx = base + jj * 8 + slot;          // 8 edges per sub-step
            e[jj] = (idx < s1) ? __ldg(&g_csr[idx]) : make_int2(0, 0);
        }
        float4 r[4];
        #pragma unroll
        for (int jj = 0; jj < 4; jj++)
            r[jj] = hin[e[jj].x * 4 + f4];
        #pragma unroll
        for (int jj = 0; jj < 4; jj++) {
            float ww = __int_as_float(e[jj].y);
            unsigned long long w2 = pack2(ww, ww);
            fma2(acc[0], pack2(r[jj].x, r[jj].y), w2);
            fma2(acc[1], pack2(r[jj].z, r[jj].w), w2);
        }
    }
    float2 v0 = unpack2(acc[0]), v1 = unpack2(acc[1]);
    float a0 = v0.x, a1 = v0.y, a2 = v1.x, a3 = v1.y;
    #pragma unroll
    for (int off = 4; off <= 16; off <<= 1) {        // reduce 8 slots
        a0 += __shfl_xor_sync(0xffffffffu, a0, off);
        a1 += __shfl_xor_sync(0xffffffffu, a1, off);
        a2 += __shfl_xor_sync(0xffffffffu, a2, off);
        a3 += __shfl_xor_sync(0xffffffffu, a3, off);
    }
    if (lane < 4) hout[n * 4 + f4] = make_float4(a0, a1, a2, a3);
}

// F=64, fp16 gathers: row = 64 half = 128B = 8 uint4. 8 lanes/edge, 4 slots,
// 32-edge chunks. Phase A: 8 csr loads; phase B: 8 gathers; phase C: FMA.
__global__ void k_prop64(int in_sel, int out_sel) {
    int gid = blockIdx.x * blockDim.x + threadIdx.x;
    int n = gid >> 5, lane = gid & 31;
    int f8 = lane & 7, slot = lane >> 3;
    const uint4* hin = (const uint4*)hbuf16(in_sel);   // row = 8 uint4
    int s0 = g_rowptr[n], s1 = g_rowptr[n + 1];
    unsigned long long acc[4] = {0ULL, 0ULL, 0ULL, 0ULL};
    for (int base = s0; base < s1; base += 32) {
        int2 e[8];
        #pragma unroll
        for (int jj = 0; jj < 8; jj++) {
            int idx = base + jj * 4 + slot;            // 4 edges per sub-step
            e[jj] = (idx < s1) ? __ldg(&g_csr[idx]) : make_int2(0, 0);
        }
        uint4 r[8];
        #pragma unroll
        for (int jj = 0; jj < 8; jj++)
            r[jj] = hin[e[jj].x * 8 + f8];             // 8 halves = 16B
        #pragma unroll
        for (int jj = 0; jj < 8; jj++) {
            float ww = __int_as_float(e[jj].y);
            unsigned long long w2 = pack2(ww, ww);
            float2 f0 = __half22float2(*(const __half2*)&r[jj].x);
            float2 f1 = __half22float2(*(const __half2*)&r[jj].y);
            float2 f2 = __half22float2(*(const __half2*)&r[jj].z);
            float2 f3 = __half22float2(*(const __half2*)&r[jj].w);
            fma2(acc[0], pack2(f0.x, f0.y), w2);
            fma2(acc[1], pack2(f1.x, f1.y), w2);
            fma2(acc[2], pack2(f2.x, f2.y), w2);
            fma2(acc[3], pack2(f3.x, f3.y), w2);
        }
    }
    // reduce the 4 edge-slots (packed adds)
    #pragma unroll
    for (int off = 8; off <= 16; off <<= 1) {
        #pragma unroll
        for (int i = 0; i < 4; i++) {
            unsigned long long o = __shfl_xor_sync(0xffffffffu, acc[i], off);
            acc[i] = add2(acc[i], o);
        }
    }
    if (lane < 8) {
        float2 v0 = unpack2(acc[0]), v1 = unpack2(acc[1]);
        float2 v2 = unpack2(acc[2]), v3 = unpack2(acc[3]);
        float4* o4 = (float4*)(g_h[out_sel] + (size_t)n * 64 + f8 * 8);
        o4[0] = make_float4(v0.x, v0.y, v1.x, v1.y);
        o4[1] = make_float4(v2.x, v2.y, v3.x, v3.y);
        __half2 p0 = __floats2half2_rn(v0.x, v0.y);
        __half2 p1 = __floats2half2_rn(v1.x, v1.y);
        __half2 p2 = __floats2half2_rn(v2.x, v2.y);
        __half2 p3 = __floats2half2_rn(v3.x, v3.y);
        uint4 hv;
        hv.x = *(const unsigned*)&p0;
        hv.y = *(const unsigned*)&p1;
        hv.z = *(const unsigned*)&p2;
        hv.w = *(const unsigned*)&p3;
        *(uint4*)(g_h16[out_sel] + (size_t)n * 64 + f8 * 8) = hv;
    }
}

// ------------------------- fused hop-GEMM (f32x2 pipe, R7 tile) --------------
// block: 256 threads = 256 nodes x 64 j; thread: 8 nodes x 8 j (4 j-pairs).
// Reads fp32 hops; writes fp32 output + fp16 shadow (next layer's gathers).
template <int F>
__device__ __forceinline__ void mm_body(const float* __restrict__ h0,
                                        const float* __restrict__ h1,
                                        const float* __restrict__ h2,
                                        const float* __restrict__ h3,
                                        const float* __restrict__ h4,
                                        const float* __restrict__ W,
                                        const float* __restrict__ b,
                                        float* __restrict__ out,
                                        __half* __restrict__ outh,
                                        float* shW) {
    const float* hs[5] = {h0, h1, h2, h3, h4};
    int t  = threadIdx.x;
    int n0 = blockIdx.x * 256;
    int tn = (t & 31) * 8;          // 32 node-groups
    int tj = (t >> 5) * 8;          // 8 j-groups

    unsigned long long acc2[8][4];
    #pragma unroll
    for (int p = 0; p < 8; p++)
        #pragma unroll
        for (int jp = 0; jp < 4; jp++) acc2[p][jp] = 0ULL;

    for (int k = 0; k < 5; k++) {
        __syncthreads();
        {
            const float4* Wk  = (const float4*)(W + k * F * 64);
            float4*       sh4 = (float4*)shW;
            for (int idx = t; idx < F * 16; idx += 256) sh4[idx] = Wk[idx];
        }
        __syncthreads();
        const unsigned long long* shW2 = (const unsigned long long*)shW;
        const float* hk = hs[k];
        for (int ic = 0; ic < F / 4; ic++) {
            float4 a[8];
            #pragma unroll
            for (int p = 0; p < 8; p++) {
                int n = n0 + tn + p;
                a[p] = (n < NN) ? *(const float4*)(hk + (size_t)n * F + ic * 4)
                                : make_float4(0.f, 0.f, 0.f, 0.f);
            }
            #pragma unroll
            for (int q = 0; q < 4; q++) {
                int i = ic * 4 + q;
                unsigned long long w2[4];
                #pragma unroll
                for (int jp = 0; jp < 4; jp++)
                    w2[jp] = shW2[(i * 64 + tj) / 2 + jp];
                #pragma unroll
                for (int p = 0; p < 8; p++) {
                    float av = (q == 0) ? a[p].x : (q == 1) ? a[p].y
                             : (q == 2) ? a[p].z : a[p].w;
                    unsigned long long av2 = pack2(av, av);
                    #pragma unroll
                    for (int jp = 0; jp < 4; jp++)
                        fma2(acc2[p][jp], av2, w2[jp]);
                }
            }
        }
    }
    float bb[8];
    #pragma unroll
    for (int jj = 0; jj < 8; jj++) bb[jj] = b[tj + jj];
    #pragma unroll
    for (int p = 0; p < 8; p++) {
        int n = n0 + tn + p;
        if (n < NN) {
            float y[8];
            #pragma unroll
            for (int jp = 0; jp < 4; jp++) {
                float2 v = unpack2(acc2[p][jp]);
                y[jp * 2]     = v.x + bb[jp * 2];
                y[jp * 2 + 1] = v.y + bb[jp * 2 + 1];
            }
            #pragma unroll
            for (int jj = 0; jj < 8; jj++)
                y[jj] = (y[jj] >= 0.f) ? y[jj] : 0.01f * y[jj];
            float4* o4 = (float4*)(out + (size_t)n * 64 + tj);
            o4[0] = make_float4(y[0], y[1], y[2], y[3]);
            o4[1] = make_float4(y[4], y[5], y[6], y[7]);
            __half2 p0 = __floats2half2_rn(y[0], y[1]);
            __half2 p1 = __floats2half2_rn(y[2], y[3]);
            __half2 p2 = __floats2half2_rn(y[4], y[5]);
            __half2 p3 = __floats2half2_rn(y[6], y[7]);
            uint4 hv;
            hv.x = *(const unsigned*)&p0;
            hv.y = *(const unsigned*)&p1;
            hv.z = *(const unsigned*)&p2;
            hv.w = *(const unsigned*)&p3;
            *(uint4*)(outh + (size_t)n * 64 + tj) = hv;
        }
    }
}

__global__ void k_mm16(const float* __restrict__ x,
                       const float* __restrict__ W,
                       const float* __restrict__ b) {
    __shared__ __align__(16) float shW[16 * 64];
    mm_body<16>(x, g_x16[0], g_x16[1], g_x16[2], g_x16[3],
                W, b, g_outA, g_outAh, shW);
}

__global__ void k_mm64(int in_sel, const float* __restrict__ W,
                       const float* __restrict__ b, int out_sel) {
    __shared__ __align__(16) float shW[64 * 64];
    const float* h0   = (in_sel == 4) ? g_outA : g_outB;
    float*       out  = (out_sel == 4) ? g_outA : g_outB;
    __half*      outh = (out_sel == 4) ? g_outAh : g_outBh;
    mm_body<64>(h0, g_h[0], g_h[1], g_h[2], g_h[3], W, b, out, outh, shW);
}

// ------------------------- final head + state restore ------------------------
__global__ void k_final(const float* __restrict__ Wout,
                        const float* __restrict__ bout,
                        float* __restrict__ out) {
    int gid = blockIdx.x * blockDim.x + threadIdx.x;
    int n = gid >> 5, lane = gid & 31;
    float2 v = ((const float2*)g_outA)[n * 32 + lane];
    float2 w = ((const float2*)Wout)[lane];
    float a = v.x * w.x + v.y * w.y;
    #pragma unroll
    for (int off = 16; off > 0; off >>= 1)
        a += __shfl_xor_sync(0xffffffffu, a, off);
    if (lane == 0) {
        out[n] = a + bout[0];
        g_cnt[n] = 0;            // restore zeros for next graph replay
        g_deg[n] = 0.f;
    }
}

// ------------------------- launch -------------------------------------------
extern "C" void kernel_launch(void* const* d_in, const int* in_sizes, int n_in,
                              void* d_out, int out_size) {
    const float* x    = (const float*)d_in[0];
    const int*   ei   = (const int*)d_in[1];     // dtype auto-detected per warp
    const float* ew   = (const float*)d_in[2];
    const float* W1   = (const float*)d_in[4];
    const float* b1   = (const float*)d_in[5];
    const float* W2   = (const float*)d_in[6];
    const float* b2   = (const float*)d_in[7];
    const float* Wout = (const float*)d_in[8];
    const float* bout = (const float*)d_in[9];
    float*       out  = (float*)d_out;

    const int NB_E = (EE + 255) / 256;
    const int NB_W = (NN * 32) / 256;       // warp-per-node: 12500 blocks
    const int NB_M = (NN + 255) / 256;      // mm kernels: 391 blocks

    // CSR build: 3 launches (deg/cnt zeros restored by k_final each run)
    k_cntdeg <<<NB_E, 256>>>(ei, ew);       // 0
    k_scan   <<<1, 1024>>>();               // 1
    k_scatter<<<NB_E, 256>>>(ei, ew);       // 2

    // Layer 1 (F_IN=16 -> 64), all fp32
    k_prop16<<<NB_W, 256>>>(x, -1, 0);      // 3 <- ncu capture slot
    k_prop16<<<NB_W, 256>>>(x,  0, 1);
    k_prop16<<<NB_W, 256>>>(x,  1, 2);
    k_prop16<<<NB_W, 256>>>(x,  2, 3);
    k_mm16  <<<NB_M, 256>>>(x, W1, b1);

    // Layer 2 (64 -> 64): in A(4) -> out B(5), fp16 gathers
    k_prop64<<<NB_W, 256>>>(4, 0);
    k_prop64<<<NB_W, 256>>>(0, 1);
    k_prop64<<<NB_W, 256>>>(1, 2);
    k_prop64<<<NB_W, 256>>>(2, 3);
    k_mm64  <<<NB_M, 256>>>(4, W2, b2, 5);

    // Layer 3 (64 -> 64): in B(5) -> out A(4), fp16 gathers
    k_prop64<<<NB_W, 256>>>(5, 0);
    k_prop64<<<NB_W, 256>>>(0, 1);
    k_prop64<<<NB_W, 256>>>(1, 2);
    k_prop64<<<NB_W, 256>>>(2, 3);
    k_mm64  <<<NB_M, 256>>>(5, W2 + 5 * 64 * 64, b2 + 64, 4);

    // Regression head + scratch restore
    k_final<<<NB_W, 256>>>(Wout, bout, out);
}